// round 10
// baseline (speedup 1.0000x reference)
#include <cuda_runtime.h>
#include <cstdint>

// Problem shape (fixed): input1/2 [4,3,720,1280] f32, flow3/4 [4,2,720,1280] f32
namespace {
constexpr int Wd  = 1280;
constexpr int Hd  = 720;
constexpr int Bd  = 4;
constexpr int HW  = Hd * Wd;
constexpr int BHW = Bd * HW;

constexpr float INV_LE  = 255.0f / 30.0f;              // 1 / LAMBDA_E
constexpr float INV2S2  = 1.0f / (2.0f * 1.5f * 1.5f); // 1/(2*sigma_d^2)
constexpr float THRESH_ = 1e-6f;
constexpr float EPS_    = 1e-6f;

constexpr int EX = 128, EY = 8;   // errfw pixel tile; 256 threads, 4 px/thread
constexpr int TX = 32, TY = 8;    // splat tile (256 threads) — frozen round-4 config
constexpr int HLO = 8;            // splat smem halo (covers |flow| < 7)
constexpr int SWW = TX + 2 * HLO; // 48
constexpr int SWH = TY + 2 * HLO; // 24
}

// Scratch: branch-indexed. acc4 = (p_r, p_g, p_b, pw), accR = rw.
__device__ float  g_fw   [2][BHW];
__device__ float4 g_acc4 [2][BHW];
__device__ float4 g_accR4[2][BHW / 4];

// ---------------------------------------------------------------------------
// Fused: photometric error (bilinear warp) + 3x3 box + fw = exp(-(e/le)^2),
// plus zeroing of the splat accumulators. 4 px/thread, 128x8 tile.
// grid.z = b + 4*br.
// ---------------------------------------------------------------------------
__device__ __forceinline__ float photo_err(
    const float* __restrict__ i1, const float* __restrict__ i2,
    const float* __restrict__ flow, int b, int x, int y)
{
    int r = y * Wd + x;
    float u = __ldg(flow + b * 2 * HW + r);
    float v = __ldg(flow + b * 2 * HW + HW + r);

    float gx = fminf(fmaxf((float)x + u, 0.f), (float)(Wd - 1));
    float gy = fminf(fmaxf((float)y + v, 0.f), (float)(Hd - 1));
    float x0f = floorf(gx), y0f = floorf(gy);
    int x0 = (int)x0f, y0 = (int)y0f;
    int x1 = min(x0 + 1, Wd - 1), y1 = min(y0 + 1, Hd - 1);
    float wx = gx - x0f, wy = gy - y0f;
    float w00 = (1.f - wx) * (1.f - wy);
    float w01 = wx * (1.f - wy);
    float w10 = (1.f - wx) * wy;
    float w11 = wx * wy;

    const float* i2b = i2 + b * 3 * HW;
    const float* i1b = i1 + b * 3 * HW;
    float e = 0.f;
#pragma unroll
    for (int c = 0; c < 3; c++) {
        const float* ip = i2b + c * HW;
        float wv = __ldg(ip + y0 * Wd + x0) * w00 + __ldg(ip + y0 * Wd + x1) * w01
                 + __ldg(ip + y1 * Wd + x0) * w10 + __ldg(ip + y1 * Wd + x1) * w11;
        e += fabsf(__ldg(i1b + c * HW + r) - wv);
    }
    return e * (1.f / 3.f);
}

__global__ void __launch_bounds__(256) k_errfw(
    const float* __restrict__ in1, const float* __restrict__ in2,
    const float* __restrict__ fl1, const float* __restrict__ fl2)
{
    __shared__ float serr[EY + 2][EX + 2];

    int br = blockIdx.z >> 2;
    int b  = blockIdx.z & 3;
    const float* i1   = br ? in2 : in1;
    const float* i2   = br ? in1 : in2;
    const float* flow = br ? fl2 : fl1;

    int bx = blockIdx.x * EX;
    int by = blockIdx.y * EY;
    int t  = threadIdx.y * 32 + threadIdx.x;

    // fill (EY+2)x(EX+2) = 10x130 halo-err tile
    for (int idx = t; idx < (EY + 2) * (EX + 2); idx += 256) {
        int j = idx / (EX + 2);
        int i = idx - j * (EX + 2);
        int ex = bx + i - 1;
        int ey = by + j - 1;
        float e = 0.f;
        if ((unsigned)ex < (unsigned)Wd && (unsigned)ey < (unsigned)Hd)
            e = photo_err(i1, i2, flow, b, ex, ey);
        serr[j][i] = e;
    }
    __syncthreads();

    int lx = threadIdx.x, ly = threadIdx.y;
    int c0 = 4 * lx;                 // local column of first of 4 pixels

    // 6 column sums (3 rows each) cover the 4 outputs' 3x3 windows
    float cs[6];
#pragma unroll
    for (int k = 0; k < 6; k++)
        cs[k] = serr[ly][c0 + k] + serr[ly + 1][c0 + k] + serr[ly + 2][c0 + k];

    float4 fw4;
    {
        float sA = cs[0] + cs[1] + cs[2];
        float sB = cs[1] + cs[2] + cs[3];
        float sC = cs[2] + cs[3] + cs[4];
        float sD = cs[3] + cs[4] + cs[5];
        float tA = sA * (1.f / 9.f) * INV_LE;
        float tB = sB * (1.f / 9.f) * INV_LE;
        float tC = sC * (1.f / 9.f) * INV_LE;
        float tD = sD * (1.f / 9.f) * INV_LE;
        fw4 = make_float4(__expf(-tA * tA), __expf(-tB * tB),
                          __expf(-tC * tC), __expf(-tD * tD));
    }

    int x = bx + c0, y = by + ly;
    int pidx = b * HW + y * Wd + x;   // multiple of 4 -> 16B aligned

    *reinterpret_cast<float4*>(&g_fw[br][pidx]) = fw4;

    float4 z4 = make_float4(0.f, 0.f, 0.f, 0.f);
#pragma unroll
    for (int k = 0; k < 4; k++)
        g_acc4[br][pidx + k] = z4;
    g_accR4[br][pidx / 4] = z4;
}

// ---------------------------------------------------------------------------
// Forward gaussian splat — FROZEN round-4 structure (every modification since
// has regressed; it sits at the LTS atomic-op rate):
//  - colors+pw: 16 red.v4 per pixel at L2 (irreducible 16B payloads)
//  - rw: shared-memory tile (48x24, halo 8) + cp.reduce.async.bulk row flush;
//    out-of-window taps (|flow| >= 7, ~never for N(0,1)) use global atomics.
// TAO_R truncation is dead (min tap weight exp(-8/4.5)=0.169 > 0.05).
// Both branches in ONE launch, grid.z = b + 4*br.
// ---------------------------------------------------------------------------
__global__ void __launch_bounds__(TX * TY) k_splat(
    const float* __restrict__ in1, const float* __restrict__ in2,
    const float* __restrict__ fl1, const float* __restrict__ fl2)
{
    __shared__ __align__(16) float srw[SWH][SWW];

    int br = blockIdx.z >> 2;
    int b  = blockIdx.z & 3;
    const float* img  = br ? in2 : in1;
    const float* flow = br ? fl2 : fl1;

    int bx = blockIdx.x * TX;
    int by = blockIdx.y * TY;
    int lx = threadIdx.x, ly = threadIdx.y;
    int t  = ly * TX + lx;
    int x  = bx + lx, y = by + ly;
    int r  = y * Wd + x;
    int p  = b * HW + r;

    // zero smem tile
    {
        float4* sz = reinterpret_cast<float4*>(&srw[0][0]);
#pragma unroll
        for (int i = t; i < SWH * SWW / 4; i += TX * TY)
            sz[i] = make_float4(0.f, 0.f, 0.f, 0.f);
    }
    __syncthreads();

    {
        float u = __ldg(flow + b * 2 * HW + r);
        float v = __ldg(flow + b * 2 * HW + HW + r);
        float f = g_fw[br][p];

        const float* imb = img + b * 3 * HW + r;
        float s0 = __ldg(imb) * f;
        float s1 = __ldg(imb + HW) * f;
        float s2 = __ldg(imb + 2 * HW) * f;

        float tx = (float)x + u, ty = (float)y + v;
        float fx = floorf(tx), fy = floorf(ty);
        int ix0 = (int)fx - 1, iy0 = (int)fy - 1;

        float gxv[4], gyv[4];
#pragma unroll
        for (int k = 0; k < 4; k++) {
            float dx = tx - (fx + (float)(k - 1));
            float dy = ty - (fy + (float)(k - 1));
            gxv[k] = __expf(-dx * dx * INV2S2);
            gyv[k] = __expf(-dy * dy * INV2S2);
        }

        float4* acc  = g_acc4[br];
        float*  accR = reinterpret_cast<float*>(g_accR4[br]);
        int xw0 = bx - HLO, yw0 = by - HLO;

#pragma unroll
        for (int j = 0; j < 4; j++) {
            int iy = iy0 + j;
            if ((unsigned)iy >= (unsigned)Hd) continue;
            int rowb = b * HW + iy * Wd;
            float gy = gyv[j];
            int sy = iy - yw0;
#pragma unroll
            for (int i = 0; i < 4; i++) {
                int ix = ix0 + i;
                if ((unsigned)ix >= (unsigned)Wd) continue;
                float w = gxv[i] * gy;
                asm volatile("red.global.add.v4.f32 [%0], {%1, %2, %3, %4};"
                             :: "l"(acc + rowb + ix), "f"(s0 * w), "f"(s1 * w),
                                "f"(s2 * w), "f"(f * w)
                             : "memory");
                int sx = ix - xw0;
                if ((unsigned)sx < (unsigned)SWW && (unsigned)sy < (unsigned)SWH)
                    atomicAdd(&srw[sy][sx], w);
                else
                    atomicAdd(accR + rowb + ix, w);   // ~never taken for N(0,1) flow
            }
        }
    }
    __syncthreads();

    // flush rw tile: one bulk async reduce per valid row (threads 0..SWH-1)
    if (t < SWH) {
        int yy = by - HLO + t;
        if ((unsigned)yy < (unsigned)Hd) {
            int xs = max(bx - HLO, 0);
            int xe = min(bx + TX + HLO, Wd);
            int nbytes = (xe - xs) * 4;                 // multiple of 16
            float* dst = reinterpret_cast<float*>(g_accR4[br]) + b * HW + yy * Wd + xs;
            uint32_t saddr = (uint32_t)__cvta_generic_to_shared(&srw[t][xs - (bx - HLO)]);
            asm volatile("fence.proxy.async.shared::cta;" ::: "memory");
            asm volatile("cp.reduce.async.bulk.global.shared::cta.bulk_group.add.f32 "
                         "[%0], [%1], %2;"
                         :: "l"(dst), "r"(saddr), "r"(nbytes) : "memory");
            asm volatile("cp.async.bulk.commit_group;" ::: "memory");
            asm volatile("cp.async.bulk.wait_group 0;" ::: "memory");
        }
    }
}

// ---------------------------------------------------------------------------
// Final adaptive blend — 4 px/thread, fully vectorized accesses.
// ---------------------------------------------------------------------------
__global__ void __launch_bounds__(256) k_blend(float* __restrict__ out) {
    int q = blockIdx.x * 256 + threadIdx.x;   // group of 4 pixels
    if (q >= BHW / 4) return;
    int p0 = q * 4;
    int b  = p0 / HW;
    int r  = p0 - b * HW;

    float4 R1v = g_accR4[0][q];
    float4 R2v = g_accR4[1][q];
    const float* R1p = &R1v.x;
    const float* R2p = &R2v.x;

    float4 o0, o1, o2;
    float* o0p = &o0.x; float* o1p = &o1.x; float* o2p = &o2.x;

#pragma unroll
    for (int k = 0; k < 4; k++) {
        float4 A = g_acc4[0][p0 + k];
        float4 C = g_acc4[1][p0 + k];
        float w1 = A.w / (R1p[k] + THRESH_);
        float w2 = C.w / (R2p[k] + THRESH_);
        float q1 = w1 / (A.w + THRESH_);
        float q2 = w2 / (C.w + THRESH_);
        float dn = 1.f / (w1 + w2 + EPS_);
        o0p[k] = (A.x * q1 + C.x * q2) * dn;
        o1p[k] = (A.y * q1 + C.y * q2) * dn;
        o2p[k] = (A.z * q1 + C.z * q2) * dn;
    }

    float* ob = out + b * 3 * HW + r;
    *reinterpret_cast<float4*>(ob)          = o0;
    *reinterpret_cast<float4*>(ob + HW)     = o1;
    *reinterpret_cast<float4*>(ob + 2 * HW) = o2;
}

// ---------------------------------------------------------------------------
extern "C" void kernel_launch(void* const* d_in, const int* in_sizes, int n_in,
                              void* d_out, int out_size)
{
    const float* i1 = (const float*)d_in[0];
    const float* i2 = (const float*)d_in[1];
    const float* f1 = (const float*)d_in[2];
    const float* f2 = (const float*)d_in[3];
    float* out = (float*)d_out;

    dim3 ge(Wd / EX, Hd / EY, Bd * 2);
    dim3 be(32, EY, 1);
    dim3 gs(Wd / TX, Hd / TY, Bd * 2);
    dim3 bs(TX, TY, 1);
    int nb = (BHW / 4 + 255) / 256;

    k_errfw<<<ge, be>>>(i1, i2, f1, f2);   // launch 1 (both branches, zeros acc)
    k_splat<<<gs, bs>>>(i1, i2, f1, f2);   // launch 2 (both branches, merged)
    k_blend<<<nb, 256>>>(out);             // launch 3
}

// round 11
// speedup vs baseline: 1.0300x; 1.0300x over previous
#include <cuda_runtime.h>
#include <cstdint>

// Problem shape (fixed): input1/2 [4,3,720,1280] f32, flow3/4 [4,2,720,1280] f32
namespace {
constexpr int Wd  = 1280;
constexpr int Hd  = 720;
constexpr int Bd  = 4;
constexpr int HW  = Hd * Wd;
constexpr int BHW = Bd * HW;

constexpr float INV_LE  = 255.0f / 30.0f;              // 1 / LAMBDA_E
constexpr float INV2S2  = 1.0f / (2.0f * 1.5f * 1.5f); // 1/(2*sigma_d^2)
constexpr float THRESH_ = 1e-6f;
constexpr float EPS_    = 1e-6f;

constexpr int EX = 64, EY = 8;    // errfw pixel tile; 256 threads, 2 px/thread (R9 best)
constexpr int TX = 32, TY = 8;    // splat tile (256 threads) — frozen round-4 config
constexpr int HLO = 8;            // splat smem halo (covers |flow| < 7)
constexpr int SWW = TX + 2 * HLO; // 48
constexpr int SWH = TY + 2 * HLO; // 24
}

// Scratch: branch-indexed. acc4 = (p_r, p_g, p_b, pw), accR = rw.
__device__ float  g_fw   [2][BHW];
__device__ float4 g_acc4 [2][BHW];
__device__ float4 g_accR4[2][BHW / 4];

// ---------------------------------------------------------------------------
// Fused: photometric error (bilinear warp) + 3x3 box + fw = exp(-(e/le)^2),
// plus zeroing of the splat accumulators. 2 px/thread, 64x8 tile (round-9
// form — measured 98.5us, best errfw variant). grid.z = b + 4*br.
// ---------------------------------------------------------------------------
__device__ __forceinline__ float photo_err(
    const float* __restrict__ i1, const float* __restrict__ i2,
    const float* __restrict__ flow, int b, int x, int y)
{
    int r = y * Wd + x;
    float u = __ldg(flow + b * 2 * HW + r);
    float v = __ldg(flow + b * 2 * HW + HW + r);

    float gx = fminf(fmaxf((float)x + u, 0.f), (float)(Wd - 1));
    float gy = fminf(fmaxf((float)y + v, 0.f), (float)(Hd - 1));
    float x0f = floorf(gx), y0f = floorf(gy);
    int x0 = (int)x0f, y0 = (int)y0f;
    int x1 = min(x0 + 1, Wd - 1), y1 = min(y0 + 1, Hd - 1);
    float wx = gx - x0f, wy = gy - y0f;
    float w00 = (1.f - wx) * (1.f - wy);
    float w01 = wx * (1.f - wy);
    float w10 = (1.f - wx) * wy;
    float w11 = wx * wy;

    const float* i2b = i2 + b * 3 * HW;
    const float* i1b = i1 + b * 3 * HW;
    float e = 0.f;
#pragma unroll
    for (int c = 0; c < 3; c++) {
        const float* ip = i2b + c * HW;
        float wv = __ldg(ip + y0 * Wd + x0) * w00 + __ldg(ip + y0 * Wd + x1) * w01
                 + __ldg(ip + y1 * Wd + x0) * w10 + __ldg(ip + y1 * Wd + x1) * w11;
        e += fabsf(__ldg(i1b + c * HW + r) - wv);
    }
    return e * (1.f / 3.f);
}

__global__ void __launch_bounds__(256) k_errfw(
    const float* __restrict__ in1, const float* __restrict__ in2,
    const float* __restrict__ fl1, const float* __restrict__ fl2)
{
    __shared__ float serr[EY + 2][EX + 2];

    int br = blockIdx.z >> 2;
    int b  = blockIdx.z & 3;
    const float* i1   = br ? in2 : in1;
    const float* i2   = br ? in1 : in2;
    const float* flow = br ? fl2 : fl1;

    int bx = blockIdx.x * EX;
    int by = blockIdx.y * EY;
    int t  = threadIdx.y * 32 + threadIdx.x;

    // fill (EY+2)x(EX+2) = 10x66 halo-err tile
    for (int idx = t; idx < (EY + 2) * (EX + 2); idx += 256) {
        int j = idx / (EX + 2);
        int i = idx - j * (EX + 2);
        int ex = bx + i - 1;
        int ey = by + j - 1;
        float e = 0.f;
        if ((unsigned)ex < (unsigned)Wd && (unsigned)ey < (unsigned)Hd)
            e = photo_err(i1, i2, flow, b, ex, ey);
        serr[j][i] = e;
    }
    __syncthreads();

    int lx = threadIdx.x, ly = threadIdx.y;
    int c0 = 2 * lx;                 // local column of first pixel

    // column sums over 3 rows for the 4 columns covering both pixels
    float cs0 = serr[ly][c0]     + serr[ly + 1][c0]     + serr[ly + 2][c0];
    float cs1 = serr[ly][c0 + 1] + serr[ly + 1][c0 + 1] + serr[ly + 2][c0 + 1];
    float cs2 = serr[ly][c0 + 2] + serr[ly + 1][c0 + 2] + serr[ly + 2][c0 + 2];
    float cs3 = serr[ly][c0 + 3] + serr[ly + 1][c0 + 3] + serr[ly + 2][c0 + 3];

    float sA = cs0 + cs1 + cs2;
    float sB = cs1 + cs2 + cs3;
    float tA = sA * (1.f / 9.f) * INV_LE;
    float tB = sB * (1.f / 9.f) * INV_LE;

    int x = bx + c0, y = by + ly;
    int pidx = b * HW + y * Wd + x;   // even -> 8B aligned

    float2 fw2 = make_float2(__expf(-tA * tA), __expf(-tB * tB));
    *reinterpret_cast<float2*>(&g_fw[br][pidx]) = fw2;

    float4 z4 = make_float4(0.f, 0.f, 0.f, 0.f);
    g_acc4[br][pidx]     = z4;
    g_acc4[br][pidx + 1] = z4;
    *reinterpret_cast<float2*>(reinterpret_cast<float*>(g_accR4[br]) + pidx) =
        make_float2(0.f, 0.f);
}

// ---------------------------------------------------------------------------
// Forward gaussian splat — FROZEN round-4 structure (every modification since
// has regressed; it sits at the LTS atomic-op rate):
//  - colors+pw: 16 red.v4 per pixel at L2 (irreducible 16B payloads)
//  - rw: shared-memory tile (48x24, halo 8) + cp.reduce.async.bulk row flush;
//    out-of-window taps (|flow| >= 7, ~never for N(0,1)) use global atomics.
// TAO_R truncation is dead (min tap weight exp(-8/4.5)=0.169 > 0.05).
// Both branches in ONE launch, grid.z = b + 4*br.
// ---------------------------------------------------------------------------
__global__ void __launch_bounds__(TX * TY) k_splat(
    const float* __restrict__ in1, const float* __restrict__ in2,
    const float* __restrict__ fl1, const float* __restrict__ fl2)
{
    __shared__ __align__(16) float srw[SWH][SWW];

    int br = blockIdx.z >> 2;
    int b  = blockIdx.z & 3;
    const float* img  = br ? in2 : in1;
    const float* flow = br ? fl2 : fl1;

    int bx = blockIdx.x * TX;
    int by = blockIdx.y * TY;
    int lx = threadIdx.x, ly = threadIdx.y;
    int t  = ly * TX + lx;
    int x  = bx + lx, y = by + ly;
    int r  = y * Wd + x;
    int p  = b * HW + r;

    // zero smem tile
    {
        float4* sz = reinterpret_cast<float4*>(&srw[0][0]);
#pragma unroll
        for (int i = t; i < SWH * SWW / 4; i += TX * TY)
            sz[i] = make_float4(0.f, 0.f, 0.f, 0.f);
    }
    __syncthreads();

    {
        float u = __ldg(flow + b * 2 * HW + r);
        float v = __ldg(flow + b * 2 * HW + HW + r);
        float f = g_fw[br][p];

        const float* imb = img + b * 3 * HW + r;
        float s0 = __ldg(imb) * f;
        float s1 = __ldg(imb + HW) * f;
        float s2 = __ldg(imb + 2 * HW) * f;

        float tx = (float)x + u, ty = (float)y + v;
        float fx = floorf(tx), fy = floorf(ty);
        int ix0 = (int)fx - 1, iy0 = (int)fy - 1;

        float gxv[4], gyv[4];
#pragma unroll
        for (int k = 0; k < 4; k++) {
            float dx = tx - (fx + (float)(k - 1));
            float dy = ty - (fy + (float)(k - 1));
            gxv[k] = __expf(-dx * dx * INV2S2);
            gyv[k] = __expf(-dy * dy * INV2S2);
        }

        float4* acc  = g_acc4[br];
        float*  accR = reinterpret_cast<float*>(g_accR4[br]);
        int xw0 = bx - HLO, yw0 = by - HLO;

#pragma unroll
        for (int j = 0; j < 4; j++) {
            int iy = iy0 + j;
            if ((unsigned)iy >= (unsigned)Hd) continue;
            int rowb = b * HW + iy * Wd;
            float gy = gyv[j];
            int sy = iy - yw0;
#pragma unroll
            for (int i = 0; i < 4; i++) {
                int ix = ix0 + i;
                if ((unsigned)ix >= (unsigned)Wd) continue;
                float w = gxv[i] * gy;
                asm volatile("red.global.add.v4.f32 [%0], {%1, %2, %3, %4};"
                             :: "l"(acc + rowb + ix), "f"(s0 * w), "f"(s1 * w),
                                "f"(s2 * w), "f"(f * w)
                             : "memory");
                int sx = ix - xw0;
                if ((unsigned)sx < (unsigned)SWW && (unsigned)sy < (unsigned)SWH)
                    atomicAdd(&srw[sy][sx], w);
                else
                    atomicAdd(accR + rowb + ix, w);   // ~never taken for N(0,1) flow
            }
        }
    }
    __syncthreads();

    // flush rw tile: one bulk async reduce per valid row (threads 0..SWH-1)
    if (t < SWH) {
        int yy = by - HLO + t;
        if ((unsigned)yy < (unsigned)Hd) {
            int xs = max(bx - HLO, 0);
            int xe = min(bx + TX + HLO, Wd);
            int nbytes = (xe - xs) * 4;                 // multiple of 16
            float* dst = reinterpret_cast<float*>(g_accR4[br]) + b * HW + yy * Wd + xs;
            uint32_t saddr = (uint32_t)__cvta_generic_to_shared(&srw[t][xs - (bx - HLO)]);
            asm volatile("fence.proxy.async.shared::cta;" ::: "memory");
            asm volatile("cp.reduce.async.bulk.global.shared::cta.bulk_group.add.f32 "
                         "[%0], [%1], %2;"
                         :: "l"(dst), "r"(saddr), "r"(nbytes) : "memory");
            asm volatile("cp.async.bulk.commit_group;" ::: "memory");
            asm volatile("cp.async.bulk.wait_group 0;" ::: "memory");
        }
    }
}

// ---------------------------------------------------------------------------
// Final adaptive blend — 4 px/thread, fully vectorized accesses.
// ---------------------------------------------------------------------------
__global__ void __launch_bounds__(256) k_blend(float* __restrict__ out) {
    int q = blockIdx.x * 256 + threadIdx.x;   // group of 4 pixels
    if (q >= BHW / 4) return;
    int p0 = q * 4;
    int b  = p0 / HW;
    int r  = p0 - b * HW;

    float4 R1v = g_accR4[0][q];
    float4 R2v = g_accR4[1][q];
    const float* R1p = &R1v.x;
    const float* R2p = &R2v.x;

    float4 o0, o1, o2;
    float* o0p = &o0.x; float* o1p = &o1.x; float* o2p = &o2.x;

#pragma unroll
    for (int k = 0; k < 4; k++) {
        float4 A = g_acc4[0][p0 + k];
        float4 C = g_acc4[1][p0 + k];
        float w1 = A.w / (R1p[k] + THRESH_);
        float w2 = C.w / (R2p[k] + THRESH_);
        float q1 = w1 / (A.w + THRESH_);
        float q2 = w2 / (C.w + THRESH_);
        float dn = 1.f / (w1 + w2 + EPS_);
        o0p[k] = (A.x * q1 + C.x * q2) * dn;
        o1p[k] = (A.y * q1 + C.y * q2) * dn;
        o2p[k] = (A.z * q1 + C.z * q2) * dn;
    }

    float* ob = out + b * 3 * HW + r;
    *reinterpret_cast<float4*>(ob)          = o0;
    *reinterpret_cast<float4*>(ob + HW)     = o1;
    *reinterpret_cast<float4*>(ob + 2 * HW) = o2;
}

// ---------------------------------------------------------------------------
extern "C" void kernel_launch(void* const* d_in, const int* in_sizes, int n_in,
                              void* d_out, int out_size)
{
    const float* i1 = (const float*)d_in[0];
    const float* i2 = (const float*)d_in[1];
    const float* f1 = (const float*)d_in[2];
    const float* f2 = (const float*)d_in[3];
    float* out = (float*)d_out;

    dim3 ge(Wd / EX, Hd / EY, Bd * 2);
    dim3 be(32, EY, 1);
    dim3 gs(Wd / TX, Hd / TY, Bd * 2);
    dim3 bs(TX, TY, 1);
    int nb = (BHW / 4 + 255) / 256;

    k_errfw<<<ge, be>>>(i1, i2, f1, f2);   // launch 1 (both branches, zeros acc)
    k_splat<<<gs, bs>>>(i1, i2, f1, f2);   // launch 2 (both branches, merged)
    k_blend<<<nb, 256>>>(out);             // launch 3
}

// round 12
// speedup vs baseline: 1.0315x; 1.0015x over previous
#include <cuda_runtime.h>
#include <cstdint>

// Problem shape (fixed): input1/2 [4,3,720,1280] f32, flow3/4 [4,2,720,1280] f32
namespace {
constexpr int Wd  = 1280;
constexpr int Hd  = 720;
constexpr int Bd  = 4;
constexpr int HW  = Hd * Wd;
constexpr int BHW = Bd * HW;

constexpr float INV_LE  = 255.0f / 30.0f;              // 1 / LAMBDA_E
constexpr float INV2S2  = 1.0f / (2.0f * 1.5f * 1.5f); // 1/(2*sigma_d^2)
constexpr float THRESH_ = 1e-6f;
constexpr float EPS_    = 1e-6f;

constexpr int EX = 64, EY = 16;   // errfw pixel tile; 256 threads, 4 px/thread (2x2)
constexpr int TX = 32, TY = 8;    // splat tile (256 threads) — frozen round-4 config
constexpr int HLO = 8;            // splat smem halo (covers |flow| < 7)
constexpr int SWW = TX + 2 * HLO; // 48
constexpr int SWH = TY + 2 * HLO; // 24
}

// Scratch: branch-indexed. acc4 = (p_r, p_g, p_b, pw), accR = rw.
__device__ float  g_fw   [2][BHW];
__device__ float4 g_acc4 [2][BHW];
__device__ float4 g_accR4[2][BHW / 4];

// ---------------------------------------------------------------------------
// Fused: photometric error (bilinear warp) + 3x3 box + fw = exp(-(e/le)^2),
// plus zeroing of the splat accumulators. 64x16 tile, 256 threads:
// each thread does 2 px (x pair) at 2 rows (ly, ly+8). grid.z = b + 4*br.
// ---------------------------------------------------------------------------
__device__ __forceinline__ float photo_err(
    const float* __restrict__ i1, const float* __restrict__ i2,
    const float* __restrict__ flow, int b, int x, int y)
{
    int r = y * Wd + x;
    float u = __ldg(flow + b * 2 * HW + r);
    float v = __ldg(flow + b * 2 * HW + HW + r);

    float gx = fminf(fmaxf((float)x + u, 0.f), (float)(Wd - 1));
    float gy = fminf(fmaxf((float)y + v, 0.f), (float)(Hd - 1));
    float x0f = floorf(gx), y0f = floorf(gy);
    int x0 = (int)x0f, y0 = (int)y0f;
    int x1 = min(x0 + 1, Wd - 1), y1 = min(y0 + 1, Hd - 1);
    float wx = gx - x0f, wy = gy - y0f;
    float w00 = (1.f - wx) * (1.f - wy);
    float w01 = wx * (1.f - wy);
    float w10 = (1.f - wx) * wy;
    float w11 = wx * wy;

    const float* i2b = i2 + b * 3 * HW;
    const float* i1b = i1 + b * 3 * HW;
    float e = 0.f;
#pragma unroll
    for (int c = 0; c < 3; c++) {
        const float* ip = i2b + c * HW;
        float wv = __ldg(ip + y0 * Wd + x0) * w00 + __ldg(ip + y0 * Wd + x1) * w01
                 + __ldg(ip + y1 * Wd + x0) * w10 + __ldg(ip + y1 * Wd + x1) * w11;
        e += fabsf(__ldg(i1b + c * HW + r) - wv);
    }
    return e * (1.f / 3.f);
}

__global__ void __launch_bounds__(256) k_errfw(
    const float* __restrict__ in1, const float* __restrict__ in2,
    const float* __restrict__ fl1, const float* __restrict__ fl2)
{
    __shared__ float serr[EY + 2][EX + 2];

    int br = blockIdx.z >> 2;
    int b  = blockIdx.z & 3;
    const float* i1   = br ? in2 : in1;
    const float* i2   = br ? in1 : in2;
    const float* flow = br ? fl2 : fl1;

    int bx = blockIdx.x * EX;
    int by = blockIdx.y * EY;
    int t  = threadIdx.y * 32 + threadIdx.x;

    // fill (EY+2)x(EX+2) = 18x66 halo-err tile
    for (int idx = t; idx < (EY + 2) * (EX + 2); idx += 256) {
        int j = idx / (EX + 2);
        int i = idx - j * (EX + 2);
        int ex = bx + i - 1;
        int ey = by + j - 1;
        float e = 0.f;
        if ((unsigned)ex < (unsigned)Wd && (unsigned)ey < (unsigned)Hd)
            e = photo_err(i1, i2, flow, b, ex, ey);
        serr[j][i] = e;
    }
    __syncthreads();

    int lx = threadIdx.x;
    int c0 = 2 * lx;                 // local column of first pixel

#pragma unroll
    for (int kk = 0; kk < 2; kk++) {
        int ly = threadIdx.y + kk * 8;

        // column sums over 3 rows for the 4 columns covering both pixels
        float cs0 = serr[ly][c0]     + serr[ly + 1][c0]     + serr[ly + 2][c0];
        float cs1 = serr[ly][c0 + 1] + serr[ly + 1][c0 + 1] + serr[ly + 2][c0 + 1];
        float cs2 = serr[ly][c0 + 2] + serr[ly + 1][c0 + 2] + serr[ly + 2][c0 + 2];
        float cs3 = serr[ly][c0 + 3] + serr[ly + 1][c0 + 3] + serr[ly + 2][c0 + 3];

        float sA = cs0 + cs1 + cs2;
        float sB = cs1 + cs2 + cs3;
        float tA = sA * (1.f / 9.f) * INV_LE;
        float tB = sB * (1.f / 9.f) * INV_LE;

        int x = bx + c0, y = by + ly;
        int pidx = b * HW + y * Wd + x;   // even -> 8B aligned

        float2 fw2 = make_float2(__expf(-tA * tA), __expf(-tB * tB));
        *reinterpret_cast<float2*>(&g_fw[br][pidx]) = fw2;

        float4 z4 = make_float4(0.f, 0.f, 0.f, 0.f);
        g_acc4[br][pidx]     = z4;
        g_acc4[br][pidx + 1] = z4;
        *reinterpret_cast<float2*>(reinterpret_cast<float*>(g_accR4[br]) + pidx) =
            make_float2(0.f, 0.f);
    }
}

// ---------------------------------------------------------------------------
// Forward gaussian splat — FROZEN round-4 structure (every modification since
// has regressed; it sits at the L1tex/LTS atomic-op rate):
//  - colors+pw: 16 red.v4 per pixel at L2 (irreducible 16B payloads)
//  - rw: shared-memory tile (48x24, halo 8) + cp.reduce.async.bulk row flush;
//    out-of-window taps (|flow| >= 7, ~never for N(0,1)) use global atomics.
// TAO_R truncation is dead (min tap weight exp(-8/4.5)=0.169 > 0.05).
// Both branches in ONE launch, grid.z = b + 4*br.
// ---------------------------------------------------------------------------
__global__ void __launch_bounds__(TX * TY) k_splat(
    const float* __restrict__ in1, const float* __restrict__ in2,
    const float* __restrict__ fl1, const float* __restrict__ fl2)
{
    __shared__ __align__(16) float srw[SWH][SWW];

    int br = blockIdx.z >> 2;
    int b  = blockIdx.z & 3;
    const float* img  = br ? in2 : in1;
    const float* flow = br ? fl2 : fl1;

    int bx = blockIdx.x * TX;
    int by = blockIdx.y * TY;
    int lx = threadIdx.x, ly = threadIdx.y;
    int t  = ly * TX + lx;
    int x  = bx + lx, y = by + ly;
    int r  = y * Wd + x;
    int p  = b * HW + r;

    // zero smem tile
    {
        float4* sz = reinterpret_cast<float4*>(&srw[0][0]);
#pragma unroll
        for (int i = t; i < SWH * SWW / 4; i += TX * TY)
            sz[i] = make_float4(0.f, 0.f, 0.f, 0.f);
    }
    __syncthreads();

    {
        float u = __ldg(flow + b * 2 * HW + r);
        float v = __ldg(flow + b * 2 * HW + HW + r);
        float f = g_fw[br][p];

        const float* imb = img + b * 3 * HW + r;
        float s0 = __ldg(imb) * f;
        float s1 = __ldg(imb + HW) * f;
        float s2 = __ldg(imb + 2 * HW) * f;

        float tx = (float)x + u, ty = (float)y + v;
        float fx = floorf(tx), fy = floorf(ty);
        int ix0 = (int)fx - 1, iy0 = (int)fy - 1;

        float gxv[4], gyv[4];
#pragma unroll
        for (int k = 0; k < 4; k++) {
            float dx = tx - (fx + (float)(k - 1));
            float dy = ty - (fy + (float)(k - 1));
            gxv[k] = __expf(-dx * dx * INV2S2);
            gyv[k] = __expf(-dy * dy * INV2S2);
        }

        float4* acc  = g_acc4[br];
        float*  accR = reinterpret_cast<float*>(g_accR4[br]);
        int xw0 = bx - HLO, yw0 = by - HLO;

#pragma unroll
        for (int j = 0; j < 4; j++) {
            int iy = iy0 + j;
            if ((unsigned)iy >= (unsigned)Hd) continue;
            int rowb = b * HW + iy * Wd;
            float gy = gyv[j];
            int sy = iy - yw0;
#pragma unroll
            for (int i = 0; i < 4; i++) {
                int ix = ix0 + i;
                if ((unsigned)ix >= (unsigned)Wd) continue;
                float w = gxv[i] * gy;
                asm volatile("red.global.add.v4.f32 [%0], {%1, %2, %3, %4};"
                             :: "l"(acc + rowb + ix), "f"(s0 * w), "f"(s1 * w),
                                "f"(s2 * w), "f"(f * w)
                             : "memory");
                int sx = ix - xw0;
                if ((unsigned)sx < (unsigned)SWW && (unsigned)sy < (unsigned)SWH)
                    atomicAdd(&srw[sy][sx], w);
                else
                    atomicAdd(accR + rowb + ix, w);   // ~never taken for N(0,1) flow
            }
        }
    }
    __syncthreads();

    // flush rw tile: one bulk async reduce per valid row (threads 0..SWH-1)
    if (t < SWH) {
        int yy = by - HLO + t;
        if ((unsigned)yy < (unsigned)Hd) {
            int xs = max(bx - HLO, 0);
            int xe = min(bx + TX + HLO, Wd);
            int nbytes = (xe - xs) * 4;                 // multiple of 16
            float* dst = reinterpret_cast<float*>(g_accR4[br]) + b * HW + yy * Wd + xs;
            uint32_t saddr = (uint32_t)__cvta_generic_to_shared(&srw[t][xs - (bx - HLO)]);
            asm volatile("fence.proxy.async.shared::cta;" ::: "memory");
            asm volatile("cp.reduce.async.bulk.global.shared::cta.bulk_group.add.f32 "
                         "[%0], [%1], %2;"
                         :: "l"(dst), "r"(saddr), "r"(nbytes) : "memory");
            asm volatile("cp.async.bulk.commit_group;" ::: "memory");
            asm volatile("cp.async.bulk.wait_group 0;" ::: "memory");
        }
    }
}

// ---------------------------------------------------------------------------
// Final adaptive blend — 4 px/thread, fully vectorized accesses.
// ---------------------------------------------------------------------------
__global__ void __launch_bounds__(256) k_blend(float* __restrict__ out) {
    int q = blockIdx.x * 256 + threadIdx.x;   // group of 4 pixels
    if (q >= BHW / 4) return;
    int p0 = q * 4;
    int b  = p0 / HW;
    int r  = p0 - b * HW;

    float4 R1v = g_accR4[0][q];
    float4 R2v = g_accR4[1][q];
    const float* R1p = &R1v.x;
    const float* R2p = &R2v.x;

    float4 o0, o1, o2;
    float* o0p = &o0.x; float* o1p = &o1.x; float* o2p = &o2.x;

#pragma unroll
    for (int k = 0; k < 4; k++) {
        float4 A = g_acc4[0][p0 + k];
        float4 C = g_acc4[1][p0 + k];
        float w1 = A.w / (R1p[k] + THRESH_);
        float w2 = C.w / (R2p[k] + THRESH_);
        float q1 = w1 / (A.w + THRESH_);
        float q2 = w2 / (C.w + THRESH_);
        float dn = 1.f / (w1 + w2 + EPS_);
        o0p[k] = (A.x * q1 + C.x * q2) * dn;
        o1p[k] = (A.y * q1 + C.y * q2) * dn;
        o2p[k] = (A.z * q1 + C.z * q2) * dn;
    }

    float* ob = out + b * 3 * HW + r;
    *reinterpret_cast<float4*>(ob)          = o0;
    *reinterpret_cast<float4*>(ob + HW)     = o1;
    *reinterpret_cast<float4*>(ob + 2 * HW) = o2;
}

// ---------------------------------------------------------------------------
extern "C" void kernel_launch(void* const* d_in, const int* in_sizes, int n_in,
                              void* d_out, int out_size)
{
    const float* i1 = (const float*)d_in[0];
    const float* i2 = (const float*)d_in[1];
    const float* f1 = (const float*)d_in[2];
    const float* f2 = (const float*)d_in[3];
    float* out = (float*)d_out;

    dim3 ge(Wd / EX, Hd / EY, Bd * 2);
    dim3 be(32, 8, 1);
    dim3 gs(Wd / TX, Hd / TY, Bd * 2);
    dim3 bs(TX, TY, 1);
    int nb = (BHW / 4 + 255) / 256;

    k_errfw<<<ge, be>>>(i1, i2, f1, f2);   // launch 1 (both branches, zeros acc)
    k_splat<<<gs, bs>>>(i1, i2, f1, f2);   // launch 2 (both branches, merged)
    k_blend<<<nb, 256>>>(out);             // launch 3
}

// round 14
// speedup vs baseline: 1.0676x; 1.0350x over previous
#include <cuda_runtime.h>
#include <cstdint>

// Problem shape (fixed): input1/2 [4,3,720,1280] f32, flow3/4 [4,2,720,1280] f32
namespace {
constexpr int Wd  = 1280;
constexpr int Hd  = 720;
constexpr int Bd  = 4;
constexpr int HW  = Hd * Wd;
constexpr int BHW = Bd * HW;

constexpr float INV_LE  = 255.0f / 30.0f;              // 1 / LAMBDA_E
constexpr float INV2S2  = 1.0f / (2.0f * 1.5f * 1.5f); // 1/(2*sigma_d^2)
constexpr float THRESH_ = 1e-6f;
constexpr float EPS_    = 1e-6f;

constexpr int EX = 64, EY = 16;   // errfw pixel tile; 256 threads, 4 px/thread (2x2)
constexpr int TX = 32, TY = 8;    // splat tile (256 threads) — frozen round-4 config
constexpr int HLO = 8;            // splat smem halo (covers |flow| < 7)
constexpr int SWW = TX + 2 * HLO; // 48
constexpr int SWH = TY + 2 * HLO; // 24

constexpr int NEB = (Wd / EX) * (Hd / EY) * Bd;  // errfw blocks per branch = 3600
constexpr int NSB = (Wd / TX) * (Hd / TY) * Bd;  // splat blocks per branch = 14400
// shared buffer: max(errfw 18*66, splat 24*48) floats
constexpr int SMEMF = ((EY + 2) * (EX + 2) > SWH * SWW) ? (EY + 2) * (EX + 2)
                                                        : SWH * SWW;
}

// Scratch: branch-indexed. acc4 = (p_r, p_g, p_b, pw), accR = rw.
__device__ float  g_fw   [2][BHW];
__device__ float4 g_acc4 [2][BHW];
__device__ float4 g_accR4[2][BHW / 4];

// ---------------------------------------------------------------------------
// errfw body: photometric error (bilinear warp) + 3x3 box + fw, plus zeroing
// of the branch's splat accumulators. 64x16 px tile; REQUIRES blockDim (32,8).
// ---------------------------------------------------------------------------
__device__ __forceinline__ float photo_err(
    const float* __restrict__ i1, const float* __restrict__ i2,
    const float* __restrict__ flow, int b, int x, int y)
{
    int r = y * Wd + x;
    float u = __ldg(flow + b * 2 * HW + r);
    float v = __ldg(flow + b * 2 * HW + HW + r);

    float gx = fminf(fmaxf((float)x + u, 0.f), (float)(Wd - 1));
    float gy = fminf(fmaxf((float)y + v, 0.f), (float)(Hd - 1));
    float x0f = floorf(gx), y0f = floorf(gy);
    int x0 = (int)x0f, y0 = (int)y0f;
    int x1 = min(x0 + 1, Wd - 1), y1 = min(y0 + 1, Hd - 1);
    float wx = gx - x0f, wy = gy - y0f;
    float w00 = (1.f - wx) * (1.f - wy);
    float w01 = wx * (1.f - wy);
    float w10 = (1.f - wx) * wy;
    float w11 = wx * wy;

    const float* i2b = i2 + b * 3 * HW;
    const float* i1b = i1 + b * 3 * HW;
    float e = 0.f;
#pragma unroll
    for (int c = 0; c < 3; c++) {
        const float* ip = i2b + c * HW;
        float wv = __ldg(ip + y0 * Wd + x0) * w00 + __ldg(ip + y0 * Wd + x1) * w01
                 + __ldg(ip + y1 * Wd + x0) * w10 + __ldg(ip + y1 * Wd + x1) * w11;
        e += fabsf(__ldg(i1b + c * HW + r) - wv);
    }
    return e * (1.f / 3.f);
}

__device__ __forceinline__ void do_errfw(
    const float* __restrict__ i1, const float* __restrict__ i2,
    const float* __restrict__ flow, int br, int b, int bx, int by,
    float (*serr)[EX + 2])
{
    int t = threadIdx.y * 32 + threadIdx.x;

    // fill (EY+2)x(EX+2) = 18x66 halo-err tile
    for (int idx = t; idx < (EY + 2) * (EX + 2); idx += 256) {
        int j = idx / (EX + 2);
        int i = idx - j * (EX + 2);
        int ex = bx + i - 1;
        int ey = by + j - 1;
        float e = 0.f;
        if ((unsigned)ex < (unsigned)Wd && (unsigned)ey < (unsigned)Hd)
            e = photo_err(i1, i2, flow, b, ex, ey);
        serr[j][i] = e;
    }
    __syncthreads();

    int lx = threadIdx.x;
    int c0 = 2 * lx;                 // local column of first pixel

#pragma unroll
    for (int kk = 0; kk < 2; kk++) {
        int ly = threadIdx.y + kk * 8;

        float cs0 = serr[ly][c0]     + serr[ly + 1][c0]     + serr[ly + 2][c0];
        float cs1 = serr[ly][c0 + 1] + serr[ly + 1][c0 + 1] + serr[ly + 2][c0 + 1];
        float cs2 = serr[ly][c0 + 2] + serr[ly + 1][c0 + 2] + serr[ly + 2][c0 + 2];
        float cs3 = serr[ly][c0 + 3] + serr[ly + 1][c0 + 3] + serr[ly + 2][c0 + 3];

        float sA = cs0 + cs1 + cs2;
        float sB = cs1 + cs2 + cs3;
        float tA = sA * (1.f / 9.f) * INV_LE;
        float tB = sB * (1.f / 9.f) * INV_LE;

        int x = bx + c0, y = by + ly;
        int pidx = b * HW + y * Wd + x;   // even -> 8B aligned

        float2 fw2 = make_float2(__expf(-tA * tA), __expf(-tB * tB));
        *reinterpret_cast<float2*>(&g_fw[br][pidx]) = fw2;

        float4 z4 = make_float4(0.f, 0.f, 0.f, 0.f);
        g_acc4[br][pidx]     = z4;
        g_acc4[br][pidx + 1] = z4;
        *reinterpret_cast<float2*>(reinterpret_cast<float*>(g_accR4[br]) + pidx) =
            make_float2(0.f, 0.f);
    }
}

// ---------------------------------------------------------------------------
// splat body — FROZEN round-4 structure (sits at the LTS atomic-op rate):
//  - colors+pw: 16 red.v4 per pixel at L2 (irreducible 16B payloads)
//  - rw: shared-memory tile (48x24, halo 8) + cp.reduce.async.bulk row flush;
//    out-of-window taps (|flow| >= 7, ~never for N(0,1)) use global atomics.
// REQUIRES blockDim (32,8). TAO_R truncation is dead (exp(-8/4.5) > 0.05).
// ---------------------------------------------------------------------------
__device__ __forceinline__ void do_splat(
    const float* __restrict__ img, const float* __restrict__ flow,
    int br, int b, int bx, int by, float (*srw)[SWW])
{
    int lx = threadIdx.x, ly = threadIdx.y;
    int t  = ly * TX + lx;
    int x  = bx + lx, y = by + ly;
    int r  = y * Wd + x;
    int p  = b * HW + r;

    // zero smem tile
    {
        float4* sz = reinterpret_cast<float4*>(&srw[0][0]);
#pragma unroll
        for (int i = t; i < SWH * SWW / 4; i += TX * TY)
            sz[i] = make_float4(0.f, 0.f, 0.f, 0.f);
    }
    __syncthreads();

    {
        float u = __ldg(flow + b * 2 * HW + r);
        float v = __ldg(flow + b * 2 * HW + HW + r);
        float f = g_fw[br][p];

        const float* imb = img + b * 3 * HW + r;
        float s0 = __ldg(imb) * f;
        float s1 = __ldg(imb + HW) * f;
        float s2 = __ldg(imb + 2 * HW) * f;

        float tx = (float)x + u, ty = (float)y + v;
        float fx = floorf(tx), fy = floorf(ty);
        int ix0 = (int)fx - 1, iy0 = (int)fy - 1;

        float gxv[4], gyv[4];
#pragma unroll
        for (int k = 0; k < 4; k++) {
            float dx = tx - (fx + (float)(k - 1));
            float dy = ty - (fy + (float)(k - 1));
            gxv[k] = __expf(-dx * dx * INV2S2);
            gyv[k] = __expf(-dy * dy * INV2S2);
        }

        float4* acc  = g_acc4[br];
        float*  accR = reinterpret_cast<float*>(g_accR4[br]);
        int xw0 = bx - HLO, yw0 = by - HLO;

#pragma unroll
        for (int j = 0; j < 4; j++) {
            int iy = iy0 + j;
            if ((unsigned)iy >= (unsigned)Hd) continue;
            int rowb = b * HW + iy * Wd;
            float gy = gyv[j];
            int sy = iy - yw0;
#pragma unroll
            for (int i = 0; i < 4; i++) {
                int ix = ix0 + i;
                if ((unsigned)ix >= (unsigned)Wd) continue;
                float w = gxv[i] * gy;
                asm volatile("red.global.add.v4.f32 [%0], {%1, %2, %3, %4};"
                             :: "l"(acc + rowb + ix), "f"(s0 * w), "f"(s1 * w),
                                "f"(s2 * w), "f"(f * w)
                             : "memory");
                int sx = ix - xw0;
                if ((unsigned)sx < (unsigned)SWW && (unsigned)sy < (unsigned)SWH)
                    atomicAdd(&srw[sy][sx], w);
                else
                    atomicAdd(accR + rowb + ix, w);   // ~never taken for N(0,1) flow
            }
        }
    }
    __syncthreads();

    // flush rw tile: one bulk async reduce per valid row (threads 0..SWH-1)
    if (t < SWH) {
        int yy = by - HLO + t;
        if ((unsigned)yy < (unsigned)Hd) {
            int xs = max(bx - HLO, 0);
            int xe = min(bx + TX + HLO, Wd);
            int nbytes = (xe - xs) * 4;                 // multiple of 16
            float* dst = reinterpret_cast<float*>(g_accR4[br]) + b * HW + yy * Wd + xs;
            uint32_t saddr = (uint32_t)__cvta_generic_to_shared(&srw[t][xs - (bx - HLO)]);
            asm volatile("fence.proxy.async.shared::cta;" ::: "memory");
            asm volatile("cp.reduce.async.bulk.global.shared::cta.bulk_group.add.f32 "
                         "[%0], [%1], %2;"
                         :: "l"(dst), "r"(saddr), "r"(nbytes) : "memory");
            asm volatile("cp.async.bulk.commit_group;" ::: "memory");
            asm volatile("cp.async.bulk.wait_group 0;" ::: "memory");
        }
    }
}

// ---------------------------------------------------------------------------
// Launch 1: errfw branch 0 (grid 20x45x4, block 32x8)
// ---------------------------------------------------------------------------
__global__ void __launch_bounds__(256) k_errfw0(
    const float* __restrict__ in1, const float* __restrict__ in2,
    const float* __restrict__ fl1)
{
    __shared__ __align__(16) float sbuf[SMEMF];
    do_errfw(in1, in2, fl1, 0, blockIdx.z,
             blockIdx.x * EX, blockIdx.y * EY,
             reinterpret_cast<float (*)[EX + 2]>(sbuf));
}

// ---------------------------------------------------------------------------
// Launch 2 (overlap): splat branch 0 (4/5 of blocks) + errfw branch 1 (1/5).
// role = blockIdx.x % 5 interleaves the two workloads across every scheduling
// wave; splat is LTS-bound (not SM-bound) so errfw's DRAM/FMA work hides in
// its shadow. Block MUST be (32,8,1) — both bodies assume that geometry.
// ---------------------------------------------------------------------------
__global__ void __launch_bounds__(256) k_mid(
    const float* __restrict__ in1, const float* __restrict__ in2,
    const float* __restrict__ fl1, const float* __restrict__ fl2)
{
    __shared__ __align__(16) float sbuf[SMEMF];
    int bid  = blockIdx.x;
    int role = bid % 5;
    if (role == 4) {
        int e   = bid / 5;            // 0..3599
        int bxi = e % (Wd / EX);
        int rem = e / (Wd / EX);
        int byi = rem % (Hd / EY);
        int b   = rem / (Hd / EY);
        do_errfw(in2, in1, fl2, 1, b, bxi * EX, byi * EY,
                 reinterpret_cast<float (*)[EX + 2]>(sbuf));
    } else {
        int s   = (bid / 5) * 4 + role;  // 0..14399
        int bxi = s % (Wd / TX);
        int rem = s / (Wd / TX);
        int byi = rem % (Hd / TY);
        int b   = rem / (Hd / TY);
        do_splat(in1, fl1, 0, b, bxi * TX, byi * TY,
                 reinterpret_cast<float (*)[SWW]>(sbuf));
    }
}

// ---------------------------------------------------------------------------
// Launch 3: splat branch 1 (grid 40x90x4, block 32x8)
// ---------------------------------------------------------------------------
__global__ void __launch_bounds__(256) k_splat1(
    const float* __restrict__ in2, const float* __restrict__ fl2)
{
    __shared__ __align__(16) float sbuf[SMEMF];
    do_splat(in2, fl2, 1, blockIdx.z,
             blockIdx.x * TX, blockIdx.y * TY,
             reinterpret_cast<float (*)[SWW]>(sbuf));
}

// ---------------------------------------------------------------------------
// Launch 4: final adaptive blend — 4 px/thread, fully vectorized accesses.
// ---------------------------------------------------------------------------
__global__ void __launch_bounds__(256) k_blend(float* __restrict__ out) {
    int q = blockIdx.x * 256 + threadIdx.x;   // group of 4 pixels
    if (q >= BHW / 4) return;
    int p0 = q * 4;
    int b  = p0 / HW;
    int r  = p0 - b * HW;

    float4 R1v = g_accR4[0][q];
    float4 R2v = g_accR4[1][q];
    const float* R1p = &R1v.x;
    const float* R2p = &R2v.x;

    float4 o0, o1, o2;
    float* o0p = &o0.x; float* o1p = &o1.x; float* o2p = &o2.x;

#pragma unroll
    for (int k = 0; k < 4; k++) {
        float4 A = g_acc4[0][p0 + k];
        float4 C = g_acc4[1][p0 + k];
        float w1 = A.w / (R1p[k] + THRESH_);
        float w2 = C.w / (R2p[k] + THRESH_);
        float q1 = w1 / (A.w + THRESH_);
        float q2 = w2 / (C.w + THRESH_);
        float dn = 1.f / (w1 + w2 + EPS_);
        o0p[k] = (A.x * q1 + C.x * q2) * dn;
        o1p[k] = (A.y * q1 + C.y * q2) * dn;
        o2p[k] = (A.z * q1 + C.z * q2) * dn;
    }

    float* ob = out + b * 3 * HW + r;
    *reinterpret_cast<float4*>(ob)          = o0;
    *reinterpret_cast<float4*>(ob + HW)     = o1;
    *reinterpret_cast<float4*>(ob + 2 * HW) = o2;
}

// ---------------------------------------------------------------------------
extern "C" void kernel_launch(void* const* d_in, const int* in_sizes, int n_in,
                              void* d_out, int out_size)
{
    const float* i1 = (const float*)d_in[0];
    const float* i2 = (const float*)d_in[1];
    const float* f1 = (const float*)d_in[2];
    const float* f2 = (const float*)d_in[3];
    float* out = (float*)d_out;

    dim3 ge(Wd / EX, Hd / EY, Bd);    // 20 x 45 x 4
    dim3 be(32, 8, 1);
    dim3 gs(Wd / TX, Hd / TY, Bd);    // 40 x 90 x 4
    dim3 bs(TX, TY, 1);
    dim3 bm(32, 8, 1);                // k_mid MUST be (32,8): bodies assume it
    int nb = (BHW / 4 + 255) / 256;

    k_errfw0<<<ge, be>>>(i1, i2, f1);              // errfw br0
    k_mid   <<<NSB + NEB, bm>>>(i1, i2, f1, f2);   // splat br0 || errfw br1
    k_splat1<<<gs, bs>>>(i2, f2);                  // splat br1
    k_blend <<<nb, 256>>>(out);                    // blend
}